// round 1
// baseline (speedup 1.0000x reference)
#include <cuda_runtime.h>
#include <cstdint>

#define VSZ 50257
#define ESZ 1024
#define HSZ 1024
#define BSZ 64
#define TSZ 512
#define G4  4096   // 4*H

// ---------------- scratch (device globals; no allocation allowed) ----------
static __device__ float g_xw[(size_t)TSZ * BSZ * G4];   // [t*B+b][4H]  512 MB
static __device__ float g_h[2][BSZ * HSZ];
static __device__ float g_c[2][BSZ * HSZ];

// ---------------- helpers --------------------------------------------------
__device__ __forceinline__ uint32_t f2tf(float x) {
  uint32_t r;
  asm("cvt.rna.tf32.f32 %0, %1;" : "=r"(r) : "f"(x));
  return r;
}

__device__ __forceinline__ void mma8(float* c, const uint32_t* a, const uint32_t* b) {
  asm volatile(
      "mma.sync.aligned.m16n8k8.row.col.f32.tf32.tf32.f32 "
      "{%0,%1,%2,%3}, {%4,%5,%6,%7}, {%8,%9}, {%0,%1,%2,%3};"
      : "+f"(c[0]), "+f"(c[1]), "+f"(c[2]), "+f"(c[3])
      : "r"(a[0]), "r"(a[1]), "r"(a[2]), "r"(a[3]), "r"(b[0]), "r"(b[1]));
}

__device__ __forceinline__ float sigm(float x) { return 1.0f / (1.0f + expf(-x)); }

// ---------------- kernel: zero h0/c0 ---------------------------------------
__global__ void k_zero() {
  int i = blockIdx.x * blockDim.x + threadIdx.x;
  if (i < BSZ * HSZ) { g_h[0][i] = 0.0f; g_c[0][i] = 0.0f; }
}

// ---------------- kernel: pre-GEMM  XW = gather(emb) @ W_ih^T --------------
// M = T*B = 32768 (BM=128), N = 4096 (BN=128), K = 1024 (BK=32)
// 256 threads = 8 warps in 4(m) x 2(n); warp tile 32x64 (mt=2 x nt=8)
__global__ __launch_bounds__(256) void k_pre(const int* __restrict__ reviews,
                                             const float* __restrict__ emb,
                                             const float* __restrict__ W_ih) {
  __shared__ uint32_t sA[128][36];
  __shared__ uint32_t sB[128][36];

  const int tid = threadIdx.x;
  const int m0 = blockIdx.y * 128;
  const int n0 = blockIdx.x * 128;
  const int lane = tid & 31, w = tid >> 5;
  const int wm = w >> 1, wn = w & 1;      // 4 x 2
  const int gid = lane >> 2, tig = lane & 3;

  // A-tile row pointers (embedding gather), B-tile row pointers
  const float* arow[4];
  const float* brow[4];
#pragma unroll
  for (int i = 0; i < 4; i++) {
    int q = tid + i * 256;           // 0..1023 float4 chunks (128 rows x 8)
    int r = q >> 3;
    int m = m0 + r;
    int b = m & 63, t = m >> 6;
    int tok = reviews[b * TSZ + t];
    arow[i] = emb + (size_t)tok * ESZ + ((q & 7) << 2);
    brow[i] = W_ih + (size_t)(n0 + r) * ESZ + ((q & 7) << 2);
  }

  float acc[2][8][4] = {};

  for (int k0 = 0; k0 < 1024; k0 += 32) {
#pragma unroll
    for (int i = 0; i < 4; i++) {
      int q = tid + i * 256;
      int r = q >> 3, c4 = (q & 7) << 2;
      float4 va = *(const float4*)(arow[i] + k0);
      sA[r][c4 + 0] = f2tf(va.x); sA[r][c4 + 1] = f2tf(va.y);
      sA[r][c4 + 2] = f2tf(va.z); sA[r][c4 + 3] = f2tf(va.w);
      float4 vb = *(const float4*)(brow[i] + k0);
      sB[r][c4 + 0] = f2tf(vb.x); sB[r][c4 + 1] = f2tf(vb.y);
      sB[r][c4 + 2] = f2tf(vb.z); sB[r][c4 + 3] = f2tf(vb.w);
    }
    __syncthreads();
#pragma unroll
    for (int k8 = 0; k8 < 4; k8++) {
      const int kk = k8 * 8;
      uint32_t af[2][4], bf[8][2];
#pragma unroll
      for (int mt = 0; mt < 2; mt++) {
        int rm = wm * 32 + mt * 16;
        af[mt][0] = sA[rm + gid][kk + tig];
        af[mt][1] = sA[rm + gid + 8][kk + tig];
        af[mt][2] = sA[rm + gid][kk + tig + 4];
        af[mt][3] = sA[rm + gid + 8][kk + tig + 4];
      }
#pragma unroll
      for (int nt = 0; nt < 8; nt++) {
        int rn = wn * 64 + nt * 8;
        bf[nt][0] = sB[rn + gid][kk + tig];
        bf[nt][1] = sB[rn + gid][kk + tig + 4];
      }
#pragma unroll
      for (int mt = 0; mt < 2; mt++)
#pragma unroll
        for (int nt = 0; nt < 8; nt++) mma8(acc[mt][nt], af[mt], bf[nt]);
    }
    __syncthreads();
  }

  // store
#pragma unroll
  for (int mt = 0; mt < 2; mt++) {
    int r0 = m0 + wm * 32 + mt * 16 + gid;
#pragma unroll
    for (int nt = 0; nt < 8; nt++) {
      int c = n0 + wn * 64 + nt * 8 + tig * 2;
      float* C0 = g_xw + (size_t)r0 * G4 + c;
      float* C1 = g_xw + (size_t)(r0 + 8) * G4 + c;
      C0[0] = acc[mt][nt][0]; C0[1] = acc[mt][nt][1];
      C1[0] = acc[mt][nt][2]; C1[1] = acc[mt][nt][3];
    }
  }
}

// ---------------- kernel: one LSTM step ------------------------------------
// 64 CTAs; CTA bx owns h-columns [bx*16, bx*16+16) -> 64 gate rows (4 strips)
// GEMM: M=64, N=64, K=1024; warps 2(m) x 4(n), warp tile 32x16 (mt=2 x nt=2)
struct SmemStep {
  union {
    struct { uint32_t A[64][36]; uint32_t B[64][36]; } ld;
    float gates[64][64];
  };
};

__global__ __launch_bounds__(256) void k_step(const float* __restrict__ W_hh, int t) {
  __shared__ SmemStep sm;
  const int tid = threadIdx.x;
  const int p = t & 1;
  const float* __restrict__ hprev = g_h[p];
  const int j0 = blockIdx.x * 16;

  const int lane = tid & 31, w = tid >> 5;
  const int wm = w >> 2, wn = w & 3;      // 2 x 4
  const int gid = lane >> 2, tig = lane & 3;

  const float* arow[2];
  const float* brow[2];
#pragma unroll
  for (int i = 0; i < 2; i++) {
    int q = tid + i * 256;            // 0..511 chunks (64 rows x 8)
    int r = q >> 3;
    arow[i] = hprev + (size_t)r * HSZ + ((q & 7) << 2);
    int wrow = (r >> 4) * HSZ + j0 + (r & 15);   // gate strip mapping
    brow[i] = W_hh + (size_t)wrow * HSZ + ((q & 7) << 2);
  }

  float acc[2][2][4] = {};

  for (int k0 = 0; k0 < 1024; k0 += 32) {
#pragma unroll
    for (int i = 0; i < 2; i++) {
      int q = tid + i * 256;
      int r = q >> 3, c4 = (q & 7) << 2;
      float4 va = *(const float4*)(arow[i] + k0);
      sm.ld.A[r][c4 + 0] = f2tf(va.x); sm.ld.A[r][c4 + 1] = f2tf(va.y);
      sm.ld.A[r][c4 + 2] = f2tf(va.z); sm.ld.A[r][c4 + 3] = f2tf(va.w);
      float4 vb = *(const float4*)(brow[i] + k0);
      sm.ld.B[r][c4 + 0] = f2tf(vb.x); sm.ld.B[r][c4 + 1] = f2tf(vb.y);
      sm.ld.B[r][c4 + 2] = f2tf(vb.z); sm.ld.B[r][c4 + 3] = f2tf(vb.w);
    }
    __syncthreads();
#pragma unroll
    for (int k8 = 0; k8 < 4; k8++) {
      const int kk = k8 * 8;
      uint32_t af[2][4], bf[2][2];
#pragma unroll
      for (int mt = 0; mt < 2; mt++) {
        int rm = wm * 32 + mt * 16;
        af[mt][0] = sm.ld.A[rm + gid][kk + tig];
        af[mt][1] = sm.ld.A[rm + gid + 8][kk + tig];
        af[mt][2] = sm.ld.A[rm + gid][kk + tig + 4];
        af[mt][3] = sm.ld.A[rm + gid + 8][kk + tig + 4];
      }
#pragma unroll
      for (int nt = 0; nt < 2; nt++) {
        int rn = wn * 16 + nt * 8;
        bf[nt][0] = sm.ld.B[rn + gid][kk + tig];
        bf[nt][1] = sm.ld.B[rn + gid][kk + tig + 4];
      }
#pragma unroll
      for (int mt = 0; mt < 2; mt++)
#pragma unroll
        for (int nt = 0; nt < 2; nt++) mma8(acc[mt][nt], af[mt], bf[nt]);
    }
    __syncthreads();
  }

  // dump gate pre-activations (W_hh part) to smem
#pragma unroll
  for (int mt = 0; mt < 2; mt++) {
    int r = wm * 32 + mt * 16 + gid;
#pragma unroll
    for (int nt = 0; nt < 2; nt++) {
      int c = wn * 16 + nt * 8 + tig * 2;
      sm.gates[r][c]     = acc[mt][nt][0];
      sm.gates[r][c + 1] = acc[mt][nt][1];
      sm.gates[r + 8][c]     = acc[mt][nt][2];
      sm.gates[r + 8][c + 1] = acc[mt][nt][3];
    }
  }
  __syncthreads();

  // LSTM pointwise: add XW, apply cell, write ping-pong h/c
#pragma unroll
  for (int s = 0; s < 4; s++) {
    int idx = tid + s * 256;           // 64 b x 16 jj = 1024
    int b = idx >> 4, jj = idx & 15;
    int j = j0 + jj;
    const float* xw = g_xw + (size_t)(t * BSZ + b) * G4;
    float iv = sm.gates[b][jj]      + xw[j];
    float fv = sm.gates[b][16 + jj] + xw[HSZ + j];
    float gv = sm.gates[b][32 + jj] + xw[2 * HSZ + j];
    float ov = sm.gates[b][48 + jj] + xw[3 * HSZ + j];
    float cp = g_c[p][b * HSZ + j];
    float c2 = sigm(fv) * cp + sigm(iv) * tanhf(gv);
    float h2 = sigm(ov) * tanhf(c2);
    g_c[p ^ 1][b * HSZ + j] = c2;
    g_h[p ^ 1][b * HSZ + j] = h2;
  }
}

// ---------------- kernel: classifier  logits = h @ W_cls^T + b -------------
// M=64 (BM=64), N=50257 (BN=128, predicated), K=1024
// warps 2(m) x 4(n); warp tile 32x32 (mt=2 x nt=4)
__global__ __launch_bounds__(256) void k_cls(const float* __restrict__ W_cls,
                                             const float* __restrict__ b_cls,
                                             float* __restrict__ out) {
  __shared__ uint32_t sA[64][36];
  __shared__ uint32_t sB[128][36];
  const int tid = threadIdx.x;
  const int n0 = blockIdx.x * 128;
  const float* __restrict__ A = g_h[0];   // final h (T even -> parity 0)

  const int lane = tid & 31, w = tid >> 5;
  const int wm = w >> 2, wn = w & 3;
  const int gid = lane >> 2, tig = lane & 3;

  const float* arow[2];
  const float* brow[4];
#pragma unroll
  for (int i = 0; i < 2; i++) {
    int q = tid + i * 256;       // 512 chunks (64 rows x 8)
    int r = q >> 3;
    arow[i] = A + (size_t)r * HSZ + ((q & 7) << 2);
  }
#pragma unroll
  for (int i = 0; i < 4; i++) {
    int q = tid + i * 256;       // 1024 chunks (128 rows x 8)
    int r = q >> 3;
    int n = n0 + r; if (n > VSZ - 1) n = VSZ - 1;
    brow[i] = W_cls + (size_t)n * HSZ + ((q & 7) << 2);
  }

  float acc[2][4][4] = {};

  for (int k0 = 0; k0 < 1024; k0 += 32) {
#pragma unroll
    for (int i = 0; i < 2; i++) {
      int q = tid + i * 256;
      int r = q >> 3, c4 = (q & 7) << 2;
      float4 va = *(const float4*)(arow[i] + k0);
      sA[r][c4 + 0] = f2tf(va.x); sA[r][c4 + 1] = f2tf(va.y);
      sA[r][c4 + 2] = f2tf(va.z); sA[r][c4 + 3] = f2tf(va.w);
    }
#pragma unroll
    for (int i = 0; i < 4; i++) {
      int q = tid + i * 256;
      int r = q >> 3, c4 = (q & 7) << 2;
      float4 vb = *(const float4*)(brow[i] + k0);
      sB[r][c4 + 0] = f2tf(vb.x); sB[r][c4 + 1] = f2tf(vb.y);
      sB[r][c4 + 2] = f2tf(vb.z); sB[r][c4 + 3] = f2tf(vb.w);
    }
    __syncthreads();
#pragma unroll
    for (int k8 = 0; k8 < 4; k8++) {
      const int kk = k8 * 8;
      uint32_t af[2][4], bf[4][2];
#pragma unroll
      for (int mt = 0; mt < 2; mt++) {
        int rm = wm * 32 + mt * 16;
        af[mt][0] = sA[rm + gid][kk + tig];
        af[mt][1] = sA[rm + gid + 8][kk + tig];
        af[mt][2] = sA[rm + gid][kk + tig + 4];
        af[mt][3] = sA[rm + gid][kk + tig + 4];
        af[mt][3] = sA[rm + gid + 8][kk + tig + 4];
      }
#pragma unroll
      for (int nt = 0; nt < 4; nt++) {
        int rn = wn * 32 + nt * 8;
        bf[nt][0] = sB[rn + gid][kk + tig];
        bf[nt][1] = sB[rn + gid][kk + tig + 4];
      }
#pragma unroll
      for (int mt = 0; mt < 2; mt++)
#pragma unroll
        for (int nt = 0; nt < 4; nt++) mma8(acc[mt][nt], af[mt], bf[nt]);
    }
    __syncthreads();
  }

#pragma unroll
  for (int mt = 0; mt < 2; mt++) {
    int r0 = wm * 32 + mt * 16 + gid;
#pragma unroll
    for (int nt = 0; nt < 4; nt++) {
      int c = n0 + wn * 32 + nt * 8 + tig * 2;
      if (c < VSZ)     out[(size_t)r0 * VSZ + c]           = acc[mt][nt][0] + b_cls[c];
      if (c + 1 < VSZ) out[(size_t)r0 * VSZ + c + 1]       = acc[mt][nt][1] + b_cls[c + 1];
      if (c < VSZ)     out[(size_t)(r0 + 8) * VSZ + c]     = acc[mt][nt][2] + b_cls[c];
      if (c + 1 < VSZ) out[(size_t)(r0 + 8) * VSZ + c + 1] = acc[mt][nt][3] + b_cls[c + 1];
    }
  }
}

// ---------------- kernel: copy final h, c into output ----------------------
__global__ void k_tail(float* __restrict__ out) {
  int i = blockIdx.x * blockDim.x + threadIdx.x;
  const size_t OH = (size_t)BSZ * VSZ;          // 3216448
  if (i < BSZ * HSZ) {
    out[OH + i]             = g_h[0][i];
    out[OH + BSZ * HSZ + i] = g_c[0][i];
  }
}

// ---------------- launch ---------------------------------------------------
extern "C" void kernel_launch(void* const* d_in, const int* in_sizes, int n_in,
                              void* d_out, int out_size) {
  const int*   reviews = (const int*)d_in[0];
  const float* emb     = (const float*)d_in[1];
  const float* W_ih    = (const float*)d_in[2];
  const float* W_hh    = (const float*)d_in[3];
  const float* W_cls   = (const float*)d_in[4];
  const float* b_cls   = (const float*)d_in[5];
  float* out = (float*)d_out;

  k_zero<<<(BSZ * HSZ + 255) / 256, 256>>>();
  k_pre<<<dim3(G4 / 128, (TSZ * BSZ) / 128), 256>>>(reviews, emb, W_ih);
  for (int t = 0; t < TSZ; t++) k_step<<<HSZ / 16, 256>>>(W_hh, t);
  k_cls<<<(VSZ + 127) / 128, 256>>>(W_cls, b_cls, out);
  k_tail<<<(BSZ * HSZ + 255) / 256, 256>>>(out);
}

// round 2
// speedup vs baseline: 1.8378x; 1.8378x over previous
#include <cuda_runtime.h>
#include <cstdint>

#define VSZ 50257
#define ESZ 1024
#define HSZ 1024
#define BSZ 64
#define TSZ 512
#define G4  4096   // 4*H
#define NCTA 128

// ---------------- scratch (device globals; no allocation allowed) ----------
static __device__ float g_xw[(size_t)TSZ * BSZ * G4];   // [t*B+b][4H]  512 MB
static __device__ float g_h[2][BSZ * HSZ];
static __device__ float g_c[BSZ * HSZ];
static __device__ unsigned g_bar, g_epoch;

// ---------------- helpers --------------------------------------------------
__device__ __forceinline__ uint32_t f2tf(float x) {
  uint32_t r;
  asm("cvt.rna.tf32.f32 %0, %1;" : "=r"(r) : "f"(x));
  return r;
}

__device__ __forceinline__ void mma8(float* c, const uint32_t* a, const uint32_t* b) {
  asm volatile(
      "mma.sync.aligned.m16n8k8.row.col.f32.tf32.tf32.f32 "
      "{%0,%1,%2,%3}, {%4,%5,%6,%7}, {%8,%9}, {%0,%1,%2,%3};"
      : "+f"(c[0]), "+f"(c[1]), "+f"(c[2]), "+f"(c[3])
      : "r"(a[0]), "r"(a[1]), "r"(a[2]), "r"(a[3]), "r"(b[0]), "r"(b[1]));
}

__device__ __forceinline__ float sigm(float x) { return 1.0f / (1.0f + expf(-x)); }

// ---------------- kernel: zero h0 ------------------------------------------
__global__ void k_zero() {
  int i = blockIdx.x * blockDim.x + threadIdx.x;
  if (i < BSZ * HSZ) g_h[0][i] = 0.0f;
}

// ---------------- kernel: pre-GEMM  XW = gather(emb) @ W_ih^T --------------
// (unchanged from passing round-1 kernel)
__global__ __launch_bounds__(256) void k_pre(const int* __restrict__ reviews,
                                             const float* __restrict__ emb,
                                             const float* __restrict__ W_ih) {
  __shared__ uint32_t sA[128][36];
  __shared__ uint32_t sB[128][36];

  const int tid = threadIdx.x;
  const int m0 = blockIdx.y * 128;
  const int n0 = blockIdx.x * 128;
  const int lane = tid & 31, w = tid >> 5;
  const int wm = w >> 1, wn = w & 1;      // 4 x 2
  const int gid = lane >> 2, tig = lane & 3;

  const float* arow[4];
  const float* brow[4];
#pragma unroll
  for (int i = 0; i < 4; i++) {
    int q = tid + i * 256;
    int r = q >> 3;
    int m = m0 + r;
    int b = m & 63, t = m >> 6;
    int tok = reviews[b * TSZ + t];
    arow[i] = emb + (size_t)tok * ESZ + ((q & 7) << 2);
    brow[i] = W_ih + (size_t)(n0 + r) * ESZ + ((q & 7) << 2);
  }

  float acc[2][8][4] = {};

  for (int k0 = 0; k0 < 1024; k0 += 32) {
#pragma unroll
    for (int i = 0; i < 4; i++) {
      int q = tid + i * 256;
      int r = q >> 3, c4 = (q & 7) << 2;
      float4 va = *(const float4*)(arow[i] + k0);
      sA[r][c4 + 0] = f2tf(va.x); sA[r][c4 + 1] = f2tf(va.y);
      sA[r][c4 + 2] = f2tf(va.z); sA[r][c4 + 3] = f2tf(va.w);
      float4 vb = *(const float4*)(brow[i] + k0);
      sB[r][c4 + 0] = f2tf(vb.x); sB[r][c4 + 1] = f2tf(vb.y);
      sB[r][c4 + 2] = f2tf(vb.z); sB[r][c4 + 3] = f2tf(vb.w);
    }
    __syncthreads();
#pragma unroll
    for (int k8 = 0; k8 < 4; k8++) {
      const int kk = k8 * 8;
      uint32_t af[2][4], bf[8][2];
#pragma unroll
      for (int mt = 0; mt < 2; mt++) {
        int rm = wm * 32 + mt * 16;
        af[mt][0] = sA[rm + gid][kk + tig];
        af[mt][1] = sA[rm + gid + 8][kk + tig];
        af[mt][2] = sA[rm + gid][kk + tig + 4];
        af[mt][3] = sA[rm + gid + 8][kk + tig + 4];
      }
#pragma unroll
      for (int nt = 0; nt < 8; nt++) {
        int rn = wn * 64 + nt * 8;
        bf[nt][0] = sB[rn + gid][kk + tig];
        bf[nt][1] = sB[rn + gid][kk + tig + 4];
      }
#pragma unroll
      for (int mt = 0; mt < 2; mt++)
#pragma unroll
        for (int nt = 0; nt < 8; nt++) mma8(acc[mt][nt], af[mt], bf[nt]);
    }
    __syncthreads();
  }

#pragma unroll
  for (int mt = 0; mt < 2; mt++) {
    int r0 = m0 + wm * 32 + mt * 16 + gid;
#pragma unroll
    for (int nt = 0; nt < 8; nt++) {
      int c = n0 + wn * 64 + nt * 8 + tig * 2;
      float* C0 = g_xw + (size_t)r0 * G4 + c;
      float* C1 = g_xw + (size_t)(r0 + 8) * G4 + c;
      C0[0] = acc[mt][nt][0]; C0[1] = acc[mt][nt][1];
      C1[0] = acc[mt][nt][2]; C1[1] = acc[mt][nt][3];
    }
  }
}

// ---------------- kernel: persistent recurrence ----------------------------
// 128 CTAs, 1/SM. CTA bx owns h-columns [bx*8, bx*8+8) -> 32 gate rows,
// held in SMEM (tf32) for all 512 steps. c stays in registers.
// Per step: GEMM M=64,N=32,K=1024 (A = h_prev from global, double-buffered),
// fused LSTM pointwise, grid barrier.
// SMEM words: sW 32*1028 = 32896, sA 2*64*68 = 8704, sg 64*33 = 2112
#define RSM_W (32 * 1028)
#define RSM_A (64 * 68)
#define RSM_BYTES ((RSM_W + 2 * RSM_A + 64 * 33) * 4)

__global__ __launch_bounds__(256) void k_rec(const float* __restrict__ W_hh) {
  extern __shared__ uint32_t sm[];
  uint32_t* sW  = sm;
  uint32_t* sA0 = sW + RSM_W;
  uint32_t* sA1 = sA0 + RSM_A;
  float*    sg  = (float*)(sA1 + RSM_A);

  const int tid = threadIdx.x;
  const int j0 = blockIdx.x * 8;
  const int lane = tid & 31, w = tid >> 5;
  const int wm = w >> 1, wn = w & 1;          // 4(m) x 2(n)
  const int gid = lane >> 2, tig = lane & 3;

  // ---- load W_hh slice (32 rows x 1024) into SMEM as tf32, once ----
#pragma unroll 4
  for (int i = 0; i < 32; i++) {
    int e = tid + i * 256;              // float4 index over 32 rows x 256
    int r = e >> 8, cc = (e & 255) * 4;
    int wrow = (r >> 3) * HSZ + j0 + (r & 7);   // gate strip mapping
    float4 v = *(const float4*)(W_hh + (size_t)wrow * HSZ + cc);
    uint32_t* d = sW + r * 1028 + cc;
    d[0] = f2tf(v.x); d[1] = f2tf(v.y); d[2] = f2tf(v.z); d[3] = f2tf(v.w);
  }
  __syncthreads();

  float creg[2] = {0.0f, 0.0f};

  for (int t = 0; t < TSZ; t++) {
    const float* __restrict__ hp = g_h[t & 1];
    float4 pre[4];

    // preload chunk 0 (k = 0..63)
#pragma unroll
    for (int i = 0; i < 4; i++) {
      int e = tid + i * 256;            // 64 rows x 16 float4
      int r = e >> 4, c4 = (e & 15) * 4;
      pre[i] = __ldcg((const float4*)(hp + r * HSZ + c4));
    }
#pragma unroll
    for (int i = 0; i < 4; i++) {
      int e = tid + i * 256;
      int r = e >> 4, c4 = (e & 15) * 4;
      uint32_t* d = sA0 + r * 68 + c4;
      d[0] = f2tf(pre[i].x); d[1] = f2tf(pre[i].y);
      d[2] = f2tf(pre[i].z); d[3] = f2tf(pre[i].w);
    }
    __syncthreads();

    float acc[2][4] = {};
    for (int kc = 0; kc < 16; kc++) {
      uint32_t* sAc = (kc & 1) ? sA1 : sA0;
      if (kc < 15) {
#pragma unroll
        for (int i = 0; i < 4; i++) {
          int e = tid + i * 256;
          int r = e >> 4, c4 = (e & 15) * 4;
          pre[i] = __ldcg((const float4*)(hp + r * HSZ + (kc + 1) * 64 + c4));
        }
      }
#pragma unroll
      for (int k8 = 0; k8 < 8; k8++) {
        const int kk = k8 * 8;
        uint32_t af[4];
        int ra = (wm * 16 + gid) * 68 + kk + tig;
        af[0] = sAc[ra];
        af[1] = sAc[ra + 8 * 68];
        af[2] = sAc[ra + 4];
        af[3] = sAc[ra + 8 * 68 + 4];
        const int kt = kc * 64 + kk + tig;
#pragma unroll
        for (int nt = 0; nt < 2; nt++) {
          int rb = (wn * 16 + nt * 8 + gid) * 1028 + kt;
          uint32_t bf[2] = {sW[rb], sW[rb + 4]};
          mma8(acc[nt], af, bf);
        }
      }
      if (kc < 15) {
        uint32_t* dn = (kc & 1) ? sA0 : sA1;
#pragma unroll
        for (int i = 0; i < 4; i++) {
          int e = tid + i * 256;
          int r = e >> 4, c4 = (e & 15) * 4;
          uint32_t* d = dn + r * 68 + c4;
          d[0] = f2tf(pre[i].x); d[1] = f2tf(pre[i].y);
          d[2] = f2tf(pre[i].z); d[3] = f2tf(pre[i].w);
        }
      }
      __syncthreads();
    }

    // epilogue: acc -> sg (b x 32 gate-local, stride 33)
#pragma unroll
    for (int nt = 0; nt < 2; nt++) {
      int c = wn * 16 + nt * 8 + tig * 2;
      int r1 = wm * 16 + gid;
      sg[r1 * 33 + c]           = acc[nt][0];
      sg[r1 * 33 + c + 1]       = acc[nt][1];
      sg[(r1 + 8) * 33 + c]     = acc[nt][2];
      sg[(r1 + 8) * 33 + c + 1] = acc[nt][3];
    }
    __syncthreads();

    // fused LSTM pointwise; c in registers
    float* __restrict__ hn = g_h[(t + 1) & 1];
    const float* __restrict__ xwb = g_xw + (size_t)t * BSZ * G4;
#pragma unroll
    for (int s = 0; s < 2; s++) {
      int idx = tid + s * 256;          // 64 b x 8 jj
      int b = idx >> 3, jj = idx & 7, j = j0 + jj;
      const float* xw = xwb + (size_t)b * G4;
      float iv = sg[b * 33 + jj]       + __ldcg(xw + j);
      float fv = sg[b * 33 + 8 + jj]   + __ldcg(xw + HSZ + j);
      float gv = sg[b * 33 + 16 + jj]  + __ldcg(xw + 2 * HSZ + j);
      float ov = sg[b * 33 + 24 + jj]  + __ldcg(xw + 3 * HSZ + j);
      float c2 = sigm(fv) * creg[s] + sigm(iv) * tanhf(gv);
      float h2 = sigm(ov) * tanhf(c2);
      creg[s] = c2;
      __stcg(hn + b * HSZ + j, h2);
      if (t == TSZ - 1) g_c[b * HSZ + j] = c2;
    }

    // ---- grid barrier (sense-reversing, replay-safe) ----
    __threadfence();
    __syncthreads();
    if (tid == 0) {
      unsigned e = atomicAdd(&g_epoch, 0u);
      if (atomicAdd(&g_bar, 1u) == NCTA - 1) {
        atomicExch(&g_bar, 0u);
        __threadfence();
        atomicAdd(&g_epoch, 1u);
      } else {
        while (atomicAdd(&g_epoch, 0u) == e) __nanosleep(64);
      }
    }
    __syncthreads();
  }
}

// ---------------- kernel: classifier  logits = h @ W_cls^T + b -------------
__global__ __launch_bounds__(256) void k_cls(const float* __restrict__ W_cls,
                                             const float* __restrict__ b_cls,
                                             float* __restrict__ out) {
  __shared__ uint32_t sA[64][36];
  __shared__ uint32_t sB[128][36];
  const int tid = threadIdx.x;
  const int n0 = blockIdx.x * 128;
  const float* __restrict__ A = g_h[0];   // final h (T even -> parity 0)

  const int lane = tid & 31, w = tid >> 5;
  const int wm = w >> 2, wn = w & 3;
  const int gid = lane >> 2, tig = lane & 3;

  const float* arow[2];
  const float* brow[4];
#pragma unroll
  for (int i = 0; i < 2; i++) {
    int q = tid + i * 256;
    int r = q >> 3;
    arow[i] = A + (size_t)r * HSZ + ((q & 7) << 2);
  }
#pragma unroll
  for (int i = 0; i < 4; i++) {
    int q = tid + i * 256;
    int r = q >> 3;
    int n = n0 + r; if (n > VSZ - 1) n = VSZ - 1;
    brow[i] = W_cls + (size_t)n * HSZ + ((q & 7) << 2);
  }

  float acc[2][4][4] = {};

  for (int k0 = 0; k0 < 1024; k0 += 32) {
#pragma unroll
    for (int i = 0; i < 2; i++) {
      int q = tid + i * 256;
      int r = q >> 3, c4 = (q & 7) << 2;
      float4 va = *(const float4*)(arow[i] + k0);
      sA[r][c4 + 0] = f2tf(va.x); sA[r][c4 + 1] = f2tf(va.y);
      sA[r][c4 + 2] = f2tf(va.z); sA[r][c4 + 3] = f2tf(va.w);
    }
#pragma unroll
    for (int i = 0; i < 4; i++) {
      int q = tid + i * 256;
      int r = q >> 3, c4 = (q & 7) << 2;
      float4 vb = *(const float4*)(brow[i] + k0);
      sB[r][c4 + 0] = f2tf(vb.x); sB[r][c4 + 1] = f2tf(vb.y);
      sB[r][c4 + 2] = f2tf(vb.z); sB[r][c4 + 3] = f2tf(vb.w);
    }
    __syncthreads();
#pragma unroll
    for (int k8 = 0; k8 < 4; k8++) {
      const int kk = k8 * 8;
      uint32_t af[2][4], bf[4][2];
#pragma unroll
      for (int mt = 0; mt < 2; mt++) {
        int rm = wm * 32 + mt * 16;
        af[mt][0] = sA[rm + gid][kk + tig];
        af[mt][1] = sA[rm + gid + 8][kk + tig];
        af[mt][2] = sA[rm + gid][kk + tig + 4];
        af[mt][3] = sA[rm + gid + 8][kk + tig + 4];
      }
#pragma unroll
      for (int nt = 0; nt < 4; nt++) {
        int rn = wn * 32 + nt * 8;
        bf[nt][0] = sB[rn + gid][kk + tig];
        bf[nt][1] = sB[rn + gid][kk + tig + 4];
      }
#pragma unroll
      for (int mt = 0; mt < 2; mt++)
#pragma unroll
        for (int nt = 0; nt < 4; nt++) mma8(acc[mt][nt], af[mt], bf[nt]);
    }
    __syncthreads();
  }

#pragma unroll
  for (int mt = 0; mt < 2; mt++) {
    int r0 = wm * 32 + mt * 16 + gid;
#pragma unroll
    for (int nt = 0; nt < 4; nt++) {
      int c = n0 + wn * 32 + nt * 8 + tig * 2;
      if (c < VSZ)     out[(size_t)r0 * VSZ + c]           = acc[mt][nt][0] + b_cls[c];
      if (c + 1 < VSZ) out[(size_t)r0 * VSZ + c + 1]       = acc[mt][nt][1] + b_cls[c + 1];
      if (c < VSZ)     out[(size_t)(r0 + 8) * VSZ + c]     = acc[mt][nt][2] + b_cls[c];
      if (c + 1 < VSZ) out[(size_t)(r0 + 8) * VSZ + c + 1] = acc[mt][nt][3] + b_cls[c + 1];
    }
  }
}

// ---------------- kernel: copy final h, c into output ----------------------
__global__ void k_tail(float* __restrict__ out) {
  int i = blockIdx.x * blockDim.x + threadIdx.x;
  const size_t OH = (size_t)BSZ * VSZ;
  if (i < BSZ * HSZ) {
    out[OH + i]             = g_h[0][i];
    out[OH + BSZ * HSZ + i] = g_c[i];
  }
}

// ---------------- launch ---------------------------------------------------
extern "C" void kernel_launch(void* const* d_in, const int* in_sizes, int n_in,
                              void* d_out, int out_size) {
  const int*   reviews = (const int*)d_in[0];
  const float* emb     = (const float*)d_in[1];
  const float* W_ih    = (const float*)d_in[2];
  const float* W_hh    = (const float*)d_in[3];
  const float* W_cls   = (const float*)d_in[4];
  const float* b_cls   = (const float*)d_in[5];
  float* out = (float*)d_out;

  static bool attr_set = false;
  if (!attr_set) {
    cudaFuncSetAttribute(k_rec, cudaFuncAttributeMaxDynamicSharedMemorySize,
                         RSM_BYTES);
    attr_set = true;
  }

  k_zero<<<(BSZ * HSZ + 255) / 256, 256>>>();
  k_pre<<<dim3(G4 / 128, (TSZ * BSZ) / 128), 256>>>(reviews, emb, W_ih);
  k_rec<<<NCTA, 256, RSM_BYTES>>>(W_hh);
  k_cls<<<(VSZ + 127) / 128, 256>>>(W_cls, b_cls, out);
  k_tail<<<(BSZ * HSZ + 255) / 256, 256>>>(out);
}

// round 4
// speedup vs baseline: 2.3982x; 1.3050x over previous
#include <cuda_runtime.h>
#include <cstdint>

#define VSZ 50257
#define ESZ 1024
#define HSZ 1024
#define BSZ 64
#define TSZ 512
#define G4  4096   // 4*H
#define NCTA 128

// ---------------- scratch (device globals; no allocation allowed) ----------
static __device__ float g_xw[(size_t)TSZ * BSZ * G4];   // [t*B+b][4H]  512 MB
static __device__ float g_h[2][BSZ * HSZ];
static __device__ float g_c[BSZ * HSZ];
static __device__ unsigned g_bar;

// ---------------- helpers --------------------------------------------------
__device__ __forceinline__ uint32_t f2tf(float x) {
  uint32_t r;
  asm("cvt.rna.tf32.f32 %0, %1;" : "=r"(r) : "f"(x));
  return r;
}

__device__ __forceinline__ void mma8(float* c, const uint32_t* a, const uint32_t* b) {
  asm volatile(
      "mma.sync.aligned.m16n8k8.row.col.f32.tf32.tf32.f32 "
      "{%0,%1,%2,%3}, {%4,%5,%6,%7}, {%8,%9}, {%0,%1,%2,%3};"
      : "+f"(c[0]), "+f"(c[1]), "+f"(c[2]), "+f"(c[3])
      : "r"(a[0]), "r"(a[1]), "r"(a[2]), "r"(a[3]), "r"(b[0]), "r"(b[1]));
}

__device__ __forceinline__ float sigm(float x) { return 1.0f / (1.0f + expf(-x)); }

// ---------------- kernel: zero h0 + barrier counter ------------------------
__global__ void k_zero() {
  int i = blockIdx.x * blockDim.x + threadIdx.x;
  if (i == 0) g_bar = 0u;
  if (i < BSZ * HSZ) g_h[0][i] = 0.0f;
}

// ---------------- kernel: pre-GEMM  XW = gather(emb) @ W_ih^T --------------
__global__ __launch_bounds__(256) void k_pre(const int* __restrict__ reviews,
                                             const float* __restrict__ emb,
                                             const float* __restrict__ W_ih) {
  __shared__ uint32_t sA[128][36];
  __shared__ uint32_t sB[128][36];

  const int tid = threadIdx.x;
  const int m0 = blockIdx.y * 128;
  const int n0 = blockIdx.x * 128;
  const int lane = tid & 31, w = tid >> 5;
  const int wm = w >> 1, wn = w & 1;      // 4 x 2
  const int gid = lane >> 2, tig = lane & 3;

  const float* arow[4];
  const float* brow[4];
#pragma unroll
  for (int i = 0; i < 4; i++) {
    int q = tid + i * 256;
    int r = q >> 3;
    int m = m0 + r;
    int b = m & 63, t = m >> 6;
    int tok = reviews[b * TSZ + t];
    arow[i] = emb + (size_t)tok * ESZ + ((q & 7) << 2);
    brow[i] = W_ih + (size_t)(n0 + r) * ESZ + ((q & 7) << 2);
  }

  float acc[2][8][4] = {};

  for (int k0 = 0; k0 < 1024; k0 += 32) {
#pragma unroll
    for (int i = 0; i < 4; i++) {
      int q = tid + i * 256;
      int r = q >> 3, c4 = (q & 7) << 2;
      float4 va = *(const float4*)(arow[i] + k0);
      sA[r][c4 + 0] = f2tf(va.x); sA[r][c4 + 1] = f2tf(va.y);
      sA[r][c4 + 2] = f2tf(va.z); sA[r][c4 + 3] = f2tf(va.w);
      float4 vb = *(const float4*)(brow[i] + k0);
      sB[r][c4 + 0] = f2tf(vb.x); sB[r][c4 + 1] = f2tf(vb.y);
      sB[r][c4 + 2] = f2tf(vb.z); sB[r][c4 + 3] = f2tf(vb.w);
    }
    __syncthreads();
#pragma unroll
    for (int k8 = 0; k8 < 4; k8++) {
      const int kk = k8 * 8;
      uint32_t af[2][4], bf[8][2];
#pragma unroll
      for (int mt = 0; mt < 2; mt++) {
        int rm = wm * 32 + mt * 16;
        af[mt][0] = sA[rm + gid][kk + tig];
        af[mt][1] = sA[rm + gid + 8][kk + tig];
        af[mt][2] = sA[rm + gid][kk + tig + 4];
        af[mt][3] = sA[rm + gid + 8][kk + tig + 4];
      }
#pragma unroll
      for (int nt = 0; nt < 8; nt++) {
        int rn = wn * 64 + nt * 8;
        bf[nt][0] = sB[rn + gid][kk + tig];
        bf[nt][1] = sB[rn + gid][kk + tig + 4];
      }
#pragma unroll
      for (int mt = 0; mt < 2; mt++)
#pragma unroll
        for (int nt = 0; nt < 8; nt++) mma8(acc[mt][nt], af[mt], bf[nt]);
    }
    __syncthreads();
  }

#pragma unroll
  for (int mt = 0; mt < 2; mt++) {
    int r0 = m0 + wm * 32 + mt * 16 + gid;
#pragma unroll
    for (int nt = 0; nt < 8; nt++) {
      int c = n0 + wn * 64 + nt * 8 + tig * 2;
      float* C0 = g_xw + (size_t)r0 * G4 + c;
      float* C1 = g_xw + (size_t)(r0 + 8) * G4 + c;
      C0[0] = acc[mt][nt][0]; C0[1] = acc[mt][nt][1];
      C1[0] = acc[mt][nt][2]; C1[1] = acc[mt][nt][3];
    }
  }
}

// ---------------- kernel: persistent recurrence v2 -------------------------
// 128 CTAs, 1/SM. CTA bx owns h-columns [bx*8, bx*8+8) -> 32 gate rows in
// SMEM (tf32) for all 512 steps; c in registers.
// 8-way warp split-K (interleaved k8 slots): each warp computes the full
// 64x32 tile over its K/8 slice; 3-round smem tree reduction merges warps.
#define RSM_W (32 * 1028)
#define RSM_A (64 * 68)
#define RSM_BYTES ((RSM_W + 2 * RSM_A + 64 * 33) * 4)

__global__ __launch_bounds__(256) void k_rec(const float* __restrict__ W_hh) {
  extern __shared__ uint32_t sm[];
  uint32_t* sW  = sm;
  uint32_t* sA0 = sW + RSM_W;
  uint32_t* sA1 = sA0 + RSM_A;
  float*    sg  = (float*)(sA1 + RSM_A);
  float*    red = (float*)sA0;          // reduction buffer (reused after GEMM)

  const int tid = threadIdx.x;
  const int j0 = blockIdx.x * 8;
  const int lane = tid & 31, w = tid >> 5;     // warp w owns k8 slot w
  const int gid = lane >> 2, tig = lane & 3;
  const int kk = w * 8;                         // k offset within 64-chunk

  // ---- load W_hh slice (32 gate rows x 1024) into SMEM as tf32, once ----
#pragma unroll 4
  for (int i = 0; i < 32; i++) {
    int e = tid + i * 256;
    int r = e >> 8, cc = (e & 255) * 4;
    int wrow = (r >> 3) * HSZ + j0 + (r & 7);
    float4 v = *(const float4*)(W_hh + (size_t)wrow * HSZ + cc);
    uint32_t* d = sW + r * 1028 + cc;
    d[0] = f2tf(v.x); d[1] = f2tf(v.y); d[2] = f2tf(v.z); d[3] = f2tf(v.w);
  }
  __syncthreads();

  float creg[2] = {0.0f, 0.0f};

  for (int t = 0; t < TSZ; t++) {
    const float* __restrict__ hp = g_h[t & 1];
    const float* __restrict__ xwb = g_xw + (size_t)t * BSZ * G4;

    // prefetch this step's xw gate biases (DRAM; consumed ~3us later)
    float xwp[8];
#pragma unroll
    for (int s = 0; s < 2; s++) {
      int idx = tid + s * 256;
      int b = idx >> 3, jj = idx & 7, j = j0 + jj;
      const float* xw = xwb + (size_t)b * G4;
      xwp[s * 4 + 0] = __ldcs(xw + j);
      xwp[s * 4 + 1] = __ldcs(xw + HSZ + j);
      xwp[s * 4 + 2] = __ldcs(xw + 2 * HSZ + j);
      xwp[s * 4 + 3] = __ldcs(xw + 3 * HSZ + j);
    }

    float4 pre[4];
    // preload chunk 0 (k = 0..63)
#pragma unroll
    for (int i = 0; i < 4; i++) {
      int e = tid + i * 256;
      int r = e >> 4, c4 = (e & 15) * 4;
      pre[i] = __ldcg((const float4*)(hp + r * HSZ + c4));
    }
#pragma unroll
    for (int i = 0; i < 4; i++) {
      int e = tid + i * 256;
      int r = e >> 4, c4 = (e & 15) * 4;
      uint32_t* d = sA0 + r * 68 + c4;
      d[0] = f2tf(pre[i].x); d[1] = f2tf(pre[i].y);
      d[2] = f2tf(pre[i].z); d[3] = f2tf(pre[i].w);
    }
    __syncthreads();

    float4 acc4[4][4];
#pragma unroll
    for (int mt = 0; mt < 4; mt++)
#pragma unroll
      for (int nt = 0; nt < 4; nt++) acc4[mt][nt] = make_float4(0.f, 0.f, 0.f, 0.f);

    for (int kc = 0; kc < 16; kc++) {
      uint32_t* sAc = (kc & 1) ? sA1 : sA0;
      if (kc < 15) {
#pragma unroll
        for (int i = 0; i < 4; i++) {
          int e = tid + i * 256;
          int r = e >> 4, c4 = (e & 15) * 4;
          pre[i] = __ldcg((const float4*)(hp + r * HSZ + (kc + 1) * 64 + c4));
        }
      }
      // this warp's single k8 slot within the chunk
      {
        uint32_t af[4][4], bf[4][2];
        const int kt = kc * 64 + kk;
#pragma unroll
        for (int mt = 0; mt < 4; mt++) {
          int ra = (mt * 16 + gid) * 68 + kk + tig;
          af[mt][0] = sAc[ra];
          af[mt][1] = sAc[ra + 8 * 68];
          af[mt][2] = sAc[ra + 4];
          af[mt][3] = sAc[ra + 8 * 68 + 4];
        }
#pragma unroll
        for (int nt = 0; nt < 4; nt++) {
          int rb = (nt * 8 + gid) * 1028 + kt + tig;
          bf[nt][0] = sW[rb];
          bf[nt][1] = sW[rb + 4];
        }
#pragma unroll
        for (int mt = 0; mt < 4; mt++)
#pragma unroll
          for (int nt = 0; nt < 4; nt++)
            mma8((float*)&acc4[mt][nt], af[mt], bf[nt]);
      }
      if (kc < 15) {
        uint32_t* dn = (kc & 1) ? sA0 : sA1;
#pragma unroll
        for (int i = 0; i < 4; i++) {
          int e = tid + i * 256;
          int r = e >> 4, c4 = (e & 15) * 4;
          uint32_t* d = dn + r * 68 + c4;
          d[0] = f2tf(pre[i].x); d[1] = f2tf(pre[i].y);
          d[2] = f2tf(pre[i].z); d[3] = f2tf(pre[i].w);
        }
      }
      __syncthreads();
    }

    // ---- tree-reduce the 8 warps' partial tiles into warp 0 ----
#pragma unroll
    for (int half = 4; half >= 1; half >>= 1) {
      if (w >= half && w < 2 * half) {
#pragma unroll
        for (int mt = 0; mt < 4; mt++)
#pragma unroll
          for (int nt = 0; nt < 4; nt++)
            *(float4*)(red + (w - half) * 2048 + ((mt * 4 + nt) * 32 + lane) * 4)
                = acc4[mt][nt];
      }
      __syncthreads();
      if (w < half) {
#pragma unroll
        for (int mt = 0; mt < 4; mt++)
#pragma unroll
          for (int nt = 0; nt < 4; nt++) {
            float4 v = *(const float4*)(red + w * 2048 + ((mt * 4 + nt) * 32 + lane) * 4);
            acc4[mt][nt].x += v.x; acc4[mt][nt].y += v.y;
            acc4[mt][nt].z += v.z; acc4[mt][nt].w += v.w;
          }
      }
      __syncthreads();
    }

    // warp 0 holds the full 64x32 gate tile -> sg
    if (w == 0) {
#pragma unroll
      for (int mt = 0; mt < 4; mt++) {
        int r0 = mt * 16 + gid;
#pragma unroll
        for (int nt = 0; nt < 4; nt++) {
          int c = nt * 8 + tig * 2;
          sg[r0 * 33 + c]           = acc4[mt][nt].x;
          sg[r0 * 33 + c + 1]       = acc4[mt][nt].y;
          sg[(r0 + 8) * 33 + c]     = acc4[mt][nt].z;
          sg[(r0 + 8) * 33 + c + 1] = acc4[mt][nt].w;
        }
      }
    }
    __syncthreads();

    // fused LSTM pointwise; c in registers
    float* __restrict__ hn = g_h[(t + 1) & 1];
#pragma unroll
    for (int s = 0; s < 2; s++) {
      int idx = tid + s * 256;
      int b = idx >> 3, jj = idx & 7, j = j0 + jj;
      float iv = sg[b * 33 + jj]      + xwp[s * 4 + 0];
      float fv = sg[b * 33 + 8 + jj]  + xwp[s * 4 + 1];
      float gv = sg[b * 33 + 16 + jj] + xwp[s * 4 + 2];
      float ov = sg[b * 33 + 24 + jj] + xwp[s * 4 + 3];
      float c2 = sigm(fv) * creg[s] + sigm(iv) * tanhf(gv);
      float h2 = sigm(ov) * tanhf(c2);
      creg[s] = c2;
      __stcg(hn + b * HSZ + j, h2);
      if (t == TSZ - 1) g_c[b * HSZ + j] = c2;
    }

    // ---- grid barrier: monotonic counter + bounded-spin backoff ----
    __syncthreads();
    if (tid == 0) {
      __threadfence();
      unsigned arr = atomicAdd(&g_bar, 1u) + 1u;
      unsigned target = (unsigned)(t + 1) * NCTA;
      if (arr != target) {
        int spin = 0;
        while (*((volatile unsigned*)&g_bar) < target) {
          if (++spin > 64) { __nanosleep(32); spin = 0; }
        }
      }
      __threadfence();
    }
    __syncthreads();
  }
}

// ---------------- kernel: classifier  logits = h @ W_cls^T + b -------------
__global__ __launch_bounds__(256) void k_cls(const float* __restrict__ W_cls,
                                             const float* __restrict__ b_cls,
                                             float* __restrict__ out) {
  __shared__ uint32_t sA[64][36];
  __shared__ uint32_t sB[128][36];
  const int tid = threadIdx.x;
  const int n0 = blockIdx.x * 128;
  const float* __restrict__ A = g_h[0];   // final h (T even -> parity 0)

  const int lane = tid & 31, w = tid >> 5;
  const int wm = w >> 2, wn = w & 3;
  const int gid = lane >> 2, tig = lane & 3;

  const float* arow[2];
  const float* brow[4];
#pragma unroll
  for (int i = 0; i < 2; i++) {
    int q = tid + i * 256;
    int r = q >> 3;
    arow[i] = A + (size_t)r * HSZ + ((q & 7) << 2);
  }
#pragma unroll
  for (int i = 0; i < 4; i++) {
    int q = tid + i * 256;
    int r = q >> 3;
    int n = n0 + r; if (n > VSZ - 1) n = VSZ - 1;
    brow[i] = W_cls + (size_t)n * HSZ + ((q & 7) << 2);
  }

  float acc[2][4][4] = {};

  for (int k0 = 0; k0 < 1024; k0 += 32) {
#pragma unroll
    for (int i = 0; i < 2; i++) {
      int q = tid + i * 256;
      int r = q >> 3, c4 = (q & 7) << 2;
      float4 va = *(const float4*)(arow[i] + k0);
      sA[r][c4 + 0] = f2tf(va.x); sA[r][c4 + 1] = f2tf(va.y);
      sA[r][c4 + 2] = f2tf(va.z); sA[r][c4 + 3] = f2tf(va.w);
    }
#pragma unroll
    for (int i = 0; i < 4; i++) {
      int q = tid + i * 256;
      int r = q >> 3, c4 = (q & 7) << 2;
      float4 vb = *(const float4*)(brow[i] + k0);
      sB[r][c4 + 0] = f2tf(vb.x); sB[r][c4 + 1] = f2tf(vb.y);
      sB[r][c4 + 2] = f2tf(vb.z); sB[r][c4 + 3] = f2tf(vb.w);
    }
    __syncthreads();
#pragma unroll
    for (int k8 = 0; k8 < 4; k8++) {
      const int kk = k8 * 8;
      uint32_t af[2][4], bf[4][2];
#pragma unroll
      for (int mt = 0; mt < 2; mt++) {
        int rm = wm * 32 + mt * 16;
        af[mt][0] = sA[rm + gid][kk + tig];
        af[mt][1] = sA[rm + gid + 8][kk + tig];
        af[mt][2] = sA[rm + gid][kk + tig + 4];
        af[mt][3] = sA[rm + gid + 8][kk + tig + 4];
      }
#pragma unroll
      for (int nt = 0; nt < 4; nt++) {
        int rn = wn * 32 + nt * 8;
        bf[nt][0] = sB[rn + gid][kk + tig];
        bf[nt][1] = sB[rn + gid][kk + tig + 4];
      }
#pragma unroll
      for (int mt = 0; mt < 2; mt++)
#pragma unroll
        for (int nt = 0; nt < 4; nt++) mma8(acc[mt][nt], af[mt], bf[nt]);
    }
    __syncthreads();
  }

#pragma unroll
  for (int mt = 0; mt < 2; mt++) {
    int r0 = wm * 32 + mt * 16 + gid;
#pragma unroll
    for (int nt = 0; nt < 4; nt++) {
      int c = n0 + wn * 32 + nt * 8 + tig * 2;
      if (c < VSZ)     out[(size_t)r0 * VSZ + c]           = acc[mt][nt][0] + b_cls[c];
      if (c + 1 < VSZ) out[(size_t)r0 * VSZ + c + 1]       = acc[mt][nt][1] + b_cls[c + 1];
      if (c < VSZ)     out[(size_t)(r0 + 8) * VSZ + c]     = acc[mt][nt][2] + b_cls[c];
      if (c + 1 < VSZ) out[(size_t)(r0 + 8) * VSZ + c + 1] = acc[mt][nt][3] + b_cls[c + 1];
    }
  }
}

// ---------------- kernel: copy final h, c into output ----------------------
__global__ void k_tail(float* __restrict__ out) {
  int i = blockIdx.x * blockDim.x + threadIdx.x;
  const size_t OH = (size_t)BSZ * VSZ;
  if (i < BSZ * HSZ) {
    out[OH + i]             = g_h[0][i];
    out[OH + BSZ * HSZ + i] = g_c[i];
  }
}

// ---------------- launch ---------------------------------------------------
extern "C" void kernel_launch(void* const* d_in, const int* in_sizes, int n_in,
                              void* d_out, int out_size) {
  const int*   reviews = (const int*)d_in[0];
  const float* emb     = (const float*)d_in[1];
  const float* W_ih    = (const float*)d_in[2];
  const float* W_hh    = (const float*)d_in[3];
  const float* W_cls   = (const float*)d_in[4];
  const float* b_cls   = (const float*)d_in[5];
  float* out = (float*)d_out;

  static bool attr_set = false;
  if (!attr_set) {
    cudaFuncSetAttribute(k_rec, cudaFuncAttributeMaxDynamicSharedMemorySize,
                         RSM_BYTES);
    attr_set = true;
  }

  k_zero<<<(BSZ * HSZ + 255) / 256, 256>>>();
  k_pre<<<dim3(G4 / 128, (TSZ * BSZ) / 128), 256>>>(reviews, emb, W_ih);
  k_rec<<<NCTA, 256, RSM_BYTES>>>(W_hh);
  k_cls<<<(VSZ + 127) / 128, 256>>>(W_cls, b_cls, out);
  k_tail<<<(BSZ * HSZ + 255) / 256, 256>>>(out);
}

// round 5
// speedup vs baseline: 2.5945x; 1.0818x over previous
#include <cuda_runtime.h>
#include <cstdint>

#define VSZ 50257
#define ESZ 1024
#define HSZ 1024
#define BSZ 64
#define TSZ 512
#define G4  4096   // 4*H
#define NCTA 128

// ---------------- scratch (device globals; no allocation allowed) ----------
static __device__ float    g_xw[(size_t)TSZ * BSZ * G4];  // [t*B+b][4H]
static __device__ uint32_t g_ht[2][BSZ * HSZ];            // h as tf32 bits
static __device__ float    g_h[BSZ * HSZ];                // final h (fp32)
static __device__ float    g_c[BSZ * HSZ];                // final c (fp32)
static __device__ unsigned g_bar;

// ---------------- helpers --------------------------------------------------
__device__ __forceinline__ uint32_t f2tf(float x) {
  uint32_t r;
  asm("cvt.rna.tf32.f32 %0, %1;" : "=r"(r) : "f"(x));
  return r;
}

__device__ __forceinline__ void mma8(float* c, const uint32_t* a, const uint32_t* b) {
  asm volatile(
      "mma.sync.aligned.m16n8k8.row.col.f32.tf32.tf32.f32 "
      "{%0,%1,%2,%3}, {%4,%5,%6,%7}, {%8,%9}, {%0,%1,%2,%3};"
      : "+f"(c[0]), "+f"(c[1]), "+f"(c[2]), "+f"(c[3])
      : "r"(a[0]), "r"(a[1]), "r"(a[2]), "r"(a[3]), "r"(b[0]), "r"(b[1]));
}

__device__ __forceinline__ float sigm(float x) { return 1.0f / (1.0f + expf(-x)); }

__device__ __forceinline__ void cpa16(uint32_t smem_dst, const void* gsrc) {
  asm volatile("cp.async.cg.shared.global [%0], [%1], 16;"
               :: "r"(smem_dst), "l"(gsrc));
}

// ---------------- kernel: zero h0 (tf32) + barrier counter -----------------
__global__ void k_zero() {
  int i = blockIdx.x * blockDim.x + threadIdx.x;
  if (i == 0) g_bar = 0u;
  if (i < BSZ * HSZ) g_ht[0][i] = 0u;
}

// ---------------- kernel: pre-GEMM  XW = gather(emb) @ W_ih^T --------------
__global__ __launch_bounds__(256) void k_pre(const int* __restrict__ reviews,
                                             const float* __restrict__ emb,
                                             const float* __restrict__ W_ih) {
  __shared__ uint32_t sA[128][36];
  __shared__ uint32_t sB[128][36];

  const int tid = threadIdx.x;
  const int m0 = blockIdx.y * 128;
  const int n0 = blockIdx.x * 128;
  const int lane = tid & 31, w = tid >> 5;
  const int wm = w >> 1, wn = w & 1;      // 4 x 2
  const int gid = lane >> 2, tig = lane & 3;

  const float* arow[4];
  const float* brow[4];
#pragma unroll
  for (int i = 0; i < 4; i++) {
    int q = tid + i * 256;
    int r = q >> 3;
    int m = m0 + r;
    int b = m & 63, t = m >> 6;
    int tok = reviews[b * TSZ + t];
    arow[i] = emb + (size_t)tok * ESZ + ((q & 7) << 2);
    brow[i] = W_ih + (size_t)(n0 + r) * ESZ + ((q & 7) << 2);
  }

  float acc[2][8][4] = {};

  for (int k0 = 0; k0 < 1024; k0 += 32) {
#pragma unroll
    for (int i = 0; i < 4; i++) {
      int q = tid + i * 256;
      int r = q >> 3, c4 = (q & 7) << 2;
      float4 va = *(const float4*)(arow[i] + k0);
      sA[r][c4 + 0] = f2tf(va.x); sA[r][c4 + 1] = f2tf(va.y);
      sA[r][c4 + 2] = f2tf(va.z); sA[r][c4 + 3] = f2tf(va.w);
      float4 vb = *(const float4*)(brow[i] + k0);
      sB[r][c4 + 0] = f2tf(vb.x); sB[r][c4 + 1] = f2tf(vb.y);
      sB[r][c4 + 2] = f2tf(vb.z); sB[r][c4 + 3] = f2tf(vb.w);
    }
    __syncthreads();
#pragma unroll
    for (int k8 = 0; k8 < 4; k8++) {
      const int kk = k8 * 8;
      uint32_t af[2][4], bf[8][2];
#pragma unroll
      for (int mt = 0; mt < 2; mt++) {
        int rm = wm * 32 + mt * 16;
        af[mt][0] = sA[rm + gid][kk + tig];
        af[mt][1] = sA[rm + gid + 8][kk + tig];
        af[mt][2] = sA[rm + gid][kk + tig + 4];
        af[mt][3] = sA[rm + gid + 8][kk + tig + 4];
      }
#pragma unroll
      for (int nt = 0; nt < 8; nt++) {
        int rn = wn * 64 + nt * 8;
        bf[nt][0] = sB[rn + gid][kk + tig];
        bf[nt][1] = sB[rn + gid][kk + tig + 4];
      }
#pragma unroll
      for (int mt = 0; mt < 2; mt++)
#pragma unroll
        for (int nt = 0; nt < 8; nt++) mma8(acc[mt][nt], af[mt], bf[nt]);
    }
    __syncthreads();
  }

#pragma unroll
  for (int mt = 0; mt < 2; mt++) {
    int r0 = m0 + wm * 32 + mt * 16 + gid;
#pragma unroll
    for (int nt = 0; nt < 8; nt++) {
      int c = n0 + wn * 64 + nt * 8 + tig * 2;
      float* C0 = g_xw + (size_t)r0 * G4 + c;
      float* C1 = g_xw + (size_t)(r0 + 8) * G4 + c;
      C0[0] = acc[mt][nt][0]; C0[1] = acc[mt][nt][1];
      C1[0] = acc[mt][nt][2]; C1[1] = acc[mt][nt][3];
    }
  }
}

// ---------------- kernel: persistent recurrence v3 -------------------------
// 128 CTAs, 1/SM. CTA bx owns h-cols [bx*8, bx*8+8) -> 32 gate rows in SMEM
// (tf32, loaded once). h lives in global as tf32 (g_ht ping-pong).
// A tile streamed via cp.async into a 4-slot ring (3 chunks in flight).
// 8-way warp split-K + smem tree reduce; c in registers; grid barrier.
#define RSM_W   (32 * 1028)       // W slice words
#define CHUNK_W (64 * 68)         // one 64-col A chunk, words
#define RING_W  (4 * CHUNK_W)
#define SG_W    (64 * 33)
#define RSM_BYTES ((RSM_W + RING_W + SG_W) * 4)

__global__ __launch_bounds__(256) void k_rec(const float* __restrict__ W_hh) {
  extern __shared__ uint32_t sm[];
  uint32_t* sW   = sm;
  uint32_t* ring = sW + RSM_W;
  float*    sg   = (float*)(ring + RING_W);
  float*    red  = (float*)ring;          // reduction buffer (reused)

  const int tid = threadIdx.x;
  const int j0 = blockIdx.x * 8;
  const int lane = tid & 31, w = tid >> 5;     // warp w owns k8 slot w
  const int gid = lane >> 2, tig = lane & 3;
  const int kk = w * 8;

  const uint32_t ring_b =
      (uint32_t)__cvta_generic_to_shared(ring);   // smem byte addr of ring

  // ---- load W_hh slice (32 gate rows x 1024) into SMEM as tf32, once ----
#pragma unroll 4
  for (int i = 0; i < 32; i++) {
    int e = tid + i * 256;
    int r = e >> 8, cc = (e & 255) * 4;
    int wrow = (r >> 3) * HSZ + j0 + (r & 7);
    float4 v = *(const float4*)(W_hh + (size_t)wrow * HSZ + cc);
    uint32_t* d = sW + r * 1028 + cc;
    d[0] = f2tf(v.x); d[1] = f2tf(v.y); d[2] = f2tf(v.z); d[3] = f2tf(v.w);
  }
  __syncthreads();

  float creg[2] = {0.0f, 0.0f};

  // per-thread cp.async source/dst offsets (4 x 16B per chunk)
  int cp_r[4], cp_c4[4];
#pragma unroll
  for (int i = 0; i < 4; i++) {
    int e = tid + i * 256;
    cp_r[i] = e >> 4; cp_c4[i] = (e & 15) * 4;
  }

  for (int t = 0; t < TSZ; t++) {
    const uint32_t* __restrict__ hp = g_ht[t & 1];
    const float* __restrict__ xwb = g_xw + (size_t)t * BSZ * G4;

    // prefetch this step's xw gate biases
    float xwp[8];
#pragma unroll
    for (int s = 0; s < 2; s++) {
      int idx = tid + s * 256;
      int b = idx >> 3, jj = idx & 7, j = j0 + jj;
      const float* xw = xwb + (size_t)b * G4;
      xwp[s * 4 + 0] = __ldcs(xw + j);
      xwp[s * 4 + 1] = __ldcs(xw + HSZ + j);
      xwp[s * 4 + 2] = __ldcs(xw + 2 * HSZ + j);
      xwp[s * 4 + 3] = __ldcs(xw + 3 * HSZ + j);
    }

    // ---- prologue: issue chunks 0..2 ----
#pragma unroll
    for (int pc = 0; pc < 3; pc++) {
#pragma unroll
      for (int i = 0; i < 4; i++)
        cpa16(ring_b + (pc * CHUNK_W + cp_r[i] * 68 + cp_c4[i]) * 4,
              hp + cp_r[i] * HSZ + pc * 64 + cp_c4[i]);
      asm volatile("cp.async.commit_group;");
    }

    float4 acc4[4][4];
#pragma unroll
    for (int mt = 0; mt < 4; mt++)
#pragma unroll
      for (int nt = 0; nt < 4; nt++) acc4[mt][nt] = make_float4(0.f, 0.f, 0.f, 0.f);

    for (int kc = 0; kc < 16; kc++) {
      if (kc <= 13)      asm volatile("cp.async.wait_group 2;");
      else if (kc == 14) asm volatile("cp.async.wait_group 1;");
      else               asm volatile("cp.async.wait_group 0;");
      __syncthreads();

      if (kc < 13) {
        const int nc = kc + 3;
#pragma unroll
        for (int i = 0; i < 4; i++)
          cpa16(ring_b + (((nc & 3) * CHUNK_W) + cp_r[i] * 68 + cp_c4[i]) * 4,
                hp + cp_r[i] * HSZ + nc * 64 + cp_c4[i]);
        asm volatile("cp.async.commit_group;");
      }

      const uint32_t* sAc = ring + (kc & 3) * CHUNK_W;
      uint32_t af[4][4], bf[4][2];
      const int kt = kc * 64 + kk;
#pragma unroll
      for (int mt = 0; mt < 4; mt++) {
        int ra = (mt * 16 + gid) * 68 + kk + tig;
        af[mt][0] = sAc[ra];
        af[mt][1] = sAc[ra + 8 * 68];
        af[mt][2] = sAc[ra + 4];
        af[mt][3] = sAc[ra + 8 * 68 + 4];
      }
#pragma unroll
      for (int nt = 0; nt < 4; nt++) {
        int rb = (nt * 8 + gid) * 1028 + kt + tig;
        bf[nt][0] = sW[rb];
        bf[nt][1] = sW[rb + 4];
      }
#pragma unroll
      for (int mt = 0; mt < 4; mt++)
#pragma unroll
        for (int nt = 0; nt < 4; nt++)
          mma8((float*)&acc4[mt][nt], af[mt], bf[nt]);
    }

    // ---- tree-reduce the 8 warps' partial tiles into warp 0 ----
#pragma unroll
    for (int half = 4; half >= 1; half >>= 1) {
      if (w >= half && w < 2 * half) {
#pragma unroll
        for (int mt = 0; mt < 4; mt++)
#pragma unroll
          for (int nt = 0; nt < 4; nt++)
            *(float4*)(red + (w - half) * 2048 + ((mt * 4 + nt) * 32 + lane) * 4)
                = acc4[mt][nt];
      }
      __syncthreads();
      if (w < half) {
#pragma unroll
        for (int mt = 0; mt < 4; mt++)
#pragma unroll
          for (int nt = 0; nt < 4; nt++) {
            float4 v = *(const float4*)(red + w * 2048 + ((mt * 4 + nt) * 32 + lane) * 4);
            acc4[mt][nt].x += v.x; acc4[mt][nt].y += v.y;
            acc4[mt][nt].z += v.z; acc4[mt][nt].w += v.w;
          }
      }
      __syncthreads();
    }

    // warp 0 holds the full 64x32 gate tile -> sg
    if (w == 0) {
#pragma unroll
      for (int mt = 0; mt < 4; mt++) {
        int r0 = mt * 16 + gid;
#pragma unroll
        for (int nt = 0; nt < 4; nt++) {
          int c = nt * 8 + tig * 2;
          sg[r0 * 33 + c]           = acc4[mt][nt].x;
          sg[r0 * 33 + c + 1]       = acc4[mt][nt].y;
          sg[(r0 + 8) * 33 + c]     = acc4[mt][nt].z;
          sg[(r0 + 8) * 33 + c + 1] = acc4[mt][nt].w;
        }
      }
    }
    __syncthreads();

    // fused LSTM pointwise; c in registers; h written as tf32
    uint32_t* __restrict__ hn = g_ht[(t + 1) & 1];
#pragma unroll
    for (int s = 0; s < 2; s++) {
      int idx = tid + s * 256;
      int b = idx >> 3, jj = idx & 7, j = j0 + jj;
      float iv = sg[b * 33 + jj]      + xwp[s * 4 + 0];
      float fv = sg[b * 33 + 8 + jj]  + xwp[s * 4 + 1];
      float gv = sg[b * 33 + 16 + jj] + xwp[s * 4 + 2];
      float ov = sg[b * 33 + 24 + jj] + xwp[s * 4 + 3];
      float c2 = sigm(fv) * creg[s] + sigm(iv) * tanhf(gv);
      float h2 = sigm(ov) * tanhf(c2);
      creg[s] = c2;
      __stcg(hn + b * HSZ + j, f2tf(h2));
      if (t == TSZ - 1) {
        g_h[b * HSZ + j] = h2;
        g_c[b * HSZ + j] = c2;
      }
    }

    // ---- grid barrier: monotonic counter + bounded-spin backoff ----
    __syncthreads();
    if (tid == 0) {
      __threadfence();
      unsigned arr = atomicAdd(&g_bar, 1u) + 1u;
      unsigned target = (unsigned)(t + 1) * NCTA;
      if (arr != target) {
        int spin = 0;
        while (*((volatile unsigned*)&g_bar) < target) {
          if (++spin > 64) { __nanosleep(32); spin = 0; }
        }
      }
      __threadfence();
    }
    __syncthreads();
  }
}

// ---------------- kernel: classifier  logits = h @ W_cls^T + b -------------
__global__ __launch_bounds__(256) void k_cls(const float* __restrict__ W_cls,
                                             const float* __restrict__ b_cls,
                                             float* __restrict__ out) {
  __shared__ uint32_t sA[64][36];
  __shared__ uint32_t sB[128][36];
  const int tid = threadIdx.x;
  const int n0 = blockIdx.x * 128;
  const uint32_t* __restrict__ A = g_ht[0];   // final h, already tf32

  const int lane = tid & 31, w = tid >> 5;
  const int wm = w >> 2, wn = w & 3;
  const int gid = lane >> 2, tig = lane & 3;

  const uint32_t* arow[2];
  const float* brow[4];
#pragma unroll
  for (int i = 0; i < 2; i++) {
    int q = tid + i * 256;
    int r = q >> 3;
    arow[i] = A + (size_t)r * HSZ + ((q & 7) << 2);
  }
#pragma unroll
  for (int i = 0; i < 4; i++) {
    int q = tid + i * 256;
    int r = q >> 3;
    int n = n0 + r; if (n > VSZ - 1) n = VSZ - 1;
    brow[i] = W_cls + (size_t)n * HSZ + ((q & 7) << 2);
  }

  float acc[2][4][4] = {};

  for (int k0 = 0; k0 < 1024; k0 += 32) {
#pragma unroll
    for (int i = 0; i < 2; i++) {
      int q = tid + i * 256;
      int r = q >> 3, c4 = (q & 7) << 2;
      uint4 va = *(const uint4*)(arow[i] + k0);
      sA[r][c4 + 0] = va.x; sA[r][c4 + 1] = va.y;
      sA[r][c4 + 2] = va.z; sA[r][c4 + 3] = va.w;
    }
#pragma unroll
    for (int i = 0; i < 4; i++) {
      int q = tid + i * 256;
      int r = q >> 3, c4 = (q & 7) << 2;
      float4 vb = *(const float4*)(brow[i] + k0);
      sB[r][c4 + 0] = f2tf(vb.x); sB[r][c4 + 1] = f2tf(vb.y);
      sB[r][c4 + 2] = f2tf(vb.z); sB[r][c4 + 3] = f2tf(vb.w);
    }
    __syncthreads();
#pragma unroll
    for (int k8 = 0; k8 < 4; k8++) {
      const int kk = k8 * 8;
      uint32_t af[2][4], bf[4][2];
#pragma unroll
      for (int mt = 0; mt < 2; mt++) {
        int rm = wm * 32 + mt * 16;
        af[mt][0] = sA[rm + gid][kk + tig];
        af[mt][1] = sA[rm + gid + 8][kk + tig];
        af[mt][2] = sA[rm + gid][kk + tig + 4];
        af[mt][3] = sA[rm + gid + 8][kk + tig + 4];
      }
#pragma unroll
      for (int nt = 0; nt < 4; nt++) {
        int rn = wn * 32 + nt * 8;
        bf[nt][0] = sB[rn + gid][kk + tig];
        bf[nt][1] = sB[rn + gid][kk + tig + 4];
      }
#pragma unroll
      for (int mt = 0; mt < 2; mt++)
#pragma unroll
        for (int nt = 0; nt < 4; nt++) mma8(acc[mt][nt], af[mt], bf[nt]);
    }
    __syncthreads();
  }

#pragma unroll
  for (int mt = 0; mt < 2; mt++) {
    int r0 = wm * 32 + mt * 16 + gid;
#pragma unroll
    for (int nt = 0; nt < 4; nt++) {
      int c = n0 + wn * 32 + nt * 8 + tig * 2;
      if (c < VSZ)     out[(size_t)r0 * VSZ + c]           = acc[mt][nt][0] + b_cls[c];
      if (c + 1 < VSZ) out[(size_t)r0 * VSZ + c + 1]       = acc[mt][nt][1] + b_cls[c + 1];
      if (c < VSZ)     out[(size_t)(r0 + 8) * VSZ + c]     = acc[mt][nt][2] + b_cls[c];
      if (c + 1 < VSZ) out[(size_t)(r0 + 8) * VSZ + c + 1] = acc[mt][nt][3] + b_cls[c + 1];
    }
  }
}

// ---------------- kernel: copy final h, c into output ----------------------
__global__ void k_tail(float* __restrict__ out) {
  int i = blockIdx.x * blockDim.x + threadIdx.x;
  const size_t OH = (size_t)BSZ * VSZ;
  if (i < BSZ * HSZ) {
    out[OH + i]             = g_h[i];
    out[OH + BSZ * HSZ + i] = g_c[i];
  }
}

// ---------------- launch ---------------------------------------------------
extern "C" void kernel_launch(void* const* d_in, const int* in_sizes, int n_in,
                              void* d_out, int out_size) {
  const int*   reviews = (const int*)d_in[0];
  const float* emb     = (const float*)d_in[1];
  const float* W_ih    = (const float*)d_in[2];
  const float* W_hh    = (const float*)d_in[3];
  const float* W_cls   = (const float*)d_in[4];
  const float* b_cls   = (const float*)d_in[5];
  float* out = (float*)d_out;

  static bool attr_set = false;
  if (!attr_set) {
    cudaFuncSetAttribute(k_rec, cudaFuncAttributeMaxDynamicSharedMemorySize,
                         RSM_BYTES);
    attr_set = true;
  }

  k_zero<<<(BSZ * HSZ + 255) / 256, 256>>>();
  k_pre<<<dim3(G4 / 128, (TSZ * BSZ) / 128), 256>>>(reviews, emb, W_ih);
  k_rec<<<NCTA, 256, RSM_BYTES>>>(W_hh);
  k_cls<<<(VSZ + 127) / 128, 256>>>(W_cls, b_cls, out);
  k_tail<<<(BSZ * HSZ + 255) / 256, 256>>>(out);
}